// round 11
// baseline (speedup 1.0000x reference)
#include <cuda_runtime.h>
#include <math.h>

#define NHID 1024
#define NOUT 50257
#define MAXLEN 24
#define GRID 592                     // 148 SMs x 4 blocks, co-resident
#define NTILE ((NOUT + 7) / 8)       // 6283 row-tiles of 8
// prefetch window of out_W (float4 units): [16MB, 112MB)
#define PREF_LO (16u * 1024u * 1024u / 16u)
#define PREF_HI (112u * 1024u * 1024u / 16u)

// -------- device scratch --------
__device__ float g_cat[2 * NHID];
__device__ float g_x[NHID];
__device__ float g_gh[3 * NHID];     // W_hh@h0 + b_hh
__device__ float g_h[NHID];
__device__ float g_logits[NOUT];
__device__ float g_pm[GRID];
__device__ float g_ps[GRID];
__device__ unsigned g_bar[4];        // epoch barrier counters (never reset)
__device__ float g_sink;

__device__ __forceinline__ float wredsum(float v) {
    #pragma unroll
    for (int o = 16; o; o >>= 1) v += __shfl_xor_sync(0xffffffffu, v, o);
    return v;
}
__device__ __forceinline__ float wredmax(float v) {
    #pragma unroll
    for (int o = 16; o; o >>= 1) v = fmaxf(v, __shfl_xor_sync(0xffffffffu, v, o));
    return v;
}
__device__ __forceinline__ float sigm(float x) { return 1.f / (1.f + expf(-x)); }
__device__ __forceinline__ float dot4(float4 a, float4 b) {
    return a.x * b.x + a.y * b.y + a.z * b.z + a.w * b.w;
}

__device__ __forceinline__ void bar_arrive_wait(int id) {
    __syncthreads();
    if (threadIdx.x == 0) {
        __threadfence();
        unsigned old = atomicAdd(&g_bar[id], 1u);
        unsigned target = old - (old % GRID) + GRID;
        volatile unsigned* p = &g_bar[id];
        while (*p < target) { __nanosleep(64); }
        __threadfence();
    }
    __syncthreads();
}
__device__ __forceinline__ void bar_wait(int id, unsigned target) {
    if (threadIdx.x == 0) {
        volatile unsigned* p = &g_bar[id];
        while (*p < target) { __nanosleep(64); }
        __threadfence();
    }
    __syncthreads();
}

__global__ void __launch_bounds__(256, 4)
mega(const int* __restrict__ inp,
     const float* __restrict__ hidden,
     const float* __restrict__ enc_outs,
     const float* __restrict__ emb_W,
     const float* __restrict__ attn_W,
     const float* __restrict__ attn_b,
     const float* __restrict__ comb_W,
     const float* __restrict__ comb_b,
     const float* __restrict__ W_ih,
     const float* __restrict__ W_hh,
     const float* __restrict__ b_ih,
     const float* __restrict__ b_hh,
     const float* __restrict__ out_W,
     const float* __restrict__ out_b,
     float* __restrict__ logp,
     float* __restrict__ hout,
     float* __restrict__ attnw_out) {
    __shared__ float sAB[2 * NHID];
    __shared__ float4 sCD[512];
    __shared__ float sred[512];
    __shared__ float sscore[32];
    __shared__ float sw[MAXLEN];
    __shared__ unsigned s_tgt;
    __shared__ int s_stop;

    const int t = threadIdx.x;             // 256
    const int b = blockIdx.x;
    const int warp = t >> 5, lane = t & 31;

    if (b >= 128) {
        // ============ gh + PREFETCH PATH (blocks 128..591) ============
        if (b < 512) {
            // gh = W_hh @ h0 + b_hh : rows (b-128)*8+warp (3072 rows over 384 blocks)
            sCD[t] = ((const float4*)hidden)[t];
            __syncthreads();
            int r = (b - 128) * 8 + warp;
            const float4* w = (const float4*)(W_hh + (size_t)r * NHID);
            float acc = 0.f;
            #pragma unroll
            for (int q = 0; q < 8; q++) {
                int idx = lane + 32 * q;
                acc += dot4(__ldcs(w + idx), sCD[idx]);
            }
            acc = wredsum(acc);
            if (lane == 0) g_gh[r] = acc + b_hh[r];
        }
        __syncthreads();
        if (t == 0) {
            __threadfence();                  // gh visible before bar arrivals
            atomicAdd(&g_bar[0], 1u);
            atomicAdd(&g_bar[1], 1u);
            unsigned old = atomicAdd(&g_bar[2], 1u);
            s_tgt = old - (old % GRID) + GRID;
            s_stop = 0;
        }
        __syncthreads();
        unsigned tgt = s_tgt;

        // ---- deep-unrolled prefetch of out_W[PREF_LO..PREF_HI) ----
        {
            const float4* w4 = (const float4*)out_W;
            const unsigned stride = 464u * 256u;              // threads in prefetch group
            float acc = 0.f;
            for (unsigned i = PREF_LO + (unsigned)(b - 128) * 256u + t;
                 i < PREF_HI; i += stride * 8u) {
                #pragma unroll
                for (int j = 0; j < 8; j++) {
                    unsigned idx = i + (unsigned)j * stride;
                    if (idx < PREF_HI) {
                        float4 v = __ldcg(w4 + idx);
                        acc += v.x + v.y + v.z + v.w;
                    }
                }
                __syncthreads();
                if (t == 0 && *(volatile unsigned*)&g_bar[2] >= tgt) s_stop = 1;
                __syncthreads();
                if (s_stop) break;
            }
            if (acc == -1.2345678e35f) g_sink = acc;          // defeat DCE
        }
        bar_wait(2, tgt);
        goto phaseD;
    }

    // ================= Phase A: attention (block 0 only) =================
    if (b == 0) {
        const float4* e4 = (const float4*)(emb_W + (size_t)inp[0] * NHID);
        float4 ev0 = e4[t];
        ((float4*)sAB)[t] = ev0;
        ((float4*)g_cat)[t] = ev0;
        ((float4*)(sAB + NHID))[t] = ((const float4*)hidden)[t];
        __syncthreads();

        for (int r = warp; r < MAXLEN; r += 8) {
            const float4* w = (const float4*)(attn_W + (size_t)r * (2 * NHID));
            const float4* s4 = (const float4*)sAB;
            float acc = 0.f;
            #pragma unroll
            for (int q = 0; q < 16; q++) {
                int idx = lane + 32 * q;
                acc += dot4(w[idx], s4[idx]);
            }
            acc = wredsum(acc);
            if (lane == 0) sscore[r] = acc + attn_b[r];
        }
        __syncthreads();

        if (warp == 0) {
            float v = (lane < MAXLEN) ? sscore[lane] : -INFINITY;
            float m = wredmax(v);
            float p = (lane < MAXLEN) ? expf(v - m) : 0.f;
            float s = wredsum(p);
            float wv = p / s;
            if (lane < MAXLEN) {
                sw[lane] = wv;
                attnw_out[lane] = wv;
            }
        }
        __syncthreads();

        #pragma unroll
        for (int j = 0; j < 4; j++) {
            int col = t + 256 * j;
            float acc = 0.f;
            #pragma unroll
            for (int m2 = 0; m2 < MAXLEN; m2++)
                acc += sw[m2] * enc_outs[m2 * NHID + col];
            g_cat[NHID + col] = acc;
        }
    }
    bar_arrive_wait(0);

    // ================= Phase B: comb GEMV + relu (blocks 0..127) =================
    {
        ((float4*)sAB)[t] = ((const float4*)g_cat)[t];
        ((float4*)sAB)[t + 256] = ((const float4*)g_cat)[t + 256];
        __syncthreads();

        int row = b * 8 + warp;
        const float4* w4 = (const float4*)(comb_W + (size_t)row * (2 * NHID));
        const float4* sc4 = (const float4*)sAB;
        float acc = 0.f;
        #pragma unroll
        for (int k = 0; k < 16; k++) {
            int idx = lane + 32 * k;
            acc += dot4(__ldcs(w4 + idx), sc4[idx]);
        }
        acc = wredsum(acc);
        if (lane == 0) g_x[row] = fmaxf(acc + comb_b[row], 0.f);
    }
    bar_arrive_wait(1);

    // ================= Phase C': gi rows + gate math (blocks 0..127) =================
    {
        sCD[t] = ((const float4*)g_x)[t];
        __syncthreads();

        int k = b * 8 + warp;
        const float4* wir = (const float4*)(W_ih + (size_t)k * NHID);
        const float4* wiz = (const float4*)(W_ih + (size_t)(k + NHID) * NHID);
        const float4* win = (const float4*)(W_ih + (size_t)(k + 2 * NHID) * NHID);

        float air = 0.f, aiz = 0.f, ain = 0.f;
        #pragma unroll
        for (int q = 0; q < 8; q++) {
            int idx = lane + 32 * q;
            float4 x4 = sCD[idx];
            air += dot4(__ldcs(wir + idx), x4);
            aiz += dot4(__ldcs(wiz + idx), x4);
            ain += dot4(__ldcs(win + idx), x4);
        }
        air = wredsum(air); aiz = wredsum(aiz); ain = wredsum(ain);

        if (lane == 0) {
            float r = sigm(air + b_ih[k] + g_gh[k]);
            float z = sigm(aiz + b_ih[NHID + k] + g_gh[NHID + k]);
            float n = tanhf(ain + b_ih[2 * NHID + k] + r * g_gh[2 * NHID + k]);
            float hnew = (1.f - z) * n + z * hidden[k];
            g_h[k] = hnew;
            hout[k] = hnew;
        }
    }
    bar_arrive_wait(2);

phaseD:
    // ================= Phase D: logits GEMV + per-block online softmax =================
    {
        sCD[t] = ((const float4*)g_h)[t];
        __syncthreads();

        float mloc = -INFINITY, sloc = 0.f;
        for (int tile = b; tile < NTILE; tile += GRID) {
            int row = tile * 8 + warp;
            if (row < NOUT) {
                const float4* w = (const float4*)(out_W + (size_t)row * NHID);
                float acc = 0.f;
                #pragma unroll
                for (int k = 0; k < 8; k++) {
                    int idx = lane + 32 * k;
                    acc += dot4(__ldcs(w + idx), sCD[idx]);
                }
                acc = wredsum(acc);
                if (lane == 0) {
                    float y = acc + out_b[row];
                    g_logits[row] = y;
                    if (y > mloc) { sloc = sloc * __expf(mloc - y) + 1.f; mloc = y; }
                    else          { sloc += __expf(y - mloc); }
                }
            }
        }
        sred[t] = mloc; sred[256 + t] = sloc;
        __syncthreads();
        for (int o = 128; o; o >>= 1) {
            if (t < o) {
                float m1 = sred[t], s1 = sred[256 + t];
                float m2 = sred[t + o], s2 = sred[256 + t + o];
                float M = fmaxf(m1, m2);
                float S = (s1 > 0.f ? s1 * __expf(m1 - M) : 0.f) +
                          (s2 > 0.f ? s2 * __expf(m2 - M) : 0.f);
                sred[t] = M; sred[256 + t] = S;
            }
            __syncthreads();
        }
        if (t == 0) { g_pm[b] = sred[0]; g_ps[b] = sred[256]; }
    }
    bar_arrive_wait(3);

    // ========== Final: redundant reduce + logp write ==========
    {
        float m = -INFINITY, s = 0.f;
        for (int i = t; i < GRID; i += 256) {
            float mb = g_pm[i], sb = g_ps[i];
            if (mb > m) { s = s * __expf(m - mb) + sb; m = mb; }
            else        { s += sb * __expf(mb - m); }
        }
        sred[t] = m; sred[256 + t] = s;
        __syncthreads();
        for (int o = 128; o; o >>= 1) {
            if (t < o) {
                float m1 = sred[t], s1 = sred[256 + t];
                float m2 = sred[t + o], s2 = sred[256 + t + o];
                float M = fmaxf(m1, m2);
                float S = (s1 > 0.f ? s1 * __expf(m1 - M) : 0.f) +
                          (s2 > 0.f ? s2 * __expf(m2 - M) : 0.f);
                sred[t] = M; sred[256 + t] = S;
            }
            __syncthreads();
        }
        float C = sred[0] + logf(sred[256]);
        int i = b * 256 + t;                    // 592*256 = 151552 > NOUT
        if (i < NOUT) logp[i] = g_logits[i] - C;
    }
}

extern "C" void kernel_launch(void* const* d_in, const int* in_sizes, int n_in,
                              void* d_out, int out_size) {
    const int*   inp      = (const int*)  d_in[0];
    const float* hidden   = (const float*)d_in[1];
    const float* enc_outs = (const float*)d_in[3];
    const float* emb_W    = (const float*)d_in[4];
    const float* attn_W   = (const float*)d_in[5];
    const float* attn_b   = (const float*)d_in[6];
    const float* comb_W   = (const float*)d_in[7];
    const float* comb_b   = (const float*)d_in[8];
    const float* W_ih     = (const float*)d_in[9];
    const float* W_hh     = (const float*)d_in[10];
    const float* b_ih     = (const float*)d_in[11];
    const float* b_hh     = (const float*)d_in[12];
    const float* out_W    = (const float*)d_in[13];
    const float* out_b    = (const float*)d_in[14];

    float* out   = (float*)d_out;
    float* logp  = out;                 // [50257]
    float* hout  = out + NOUT;          // [1024]
    float* attnw = out + NOUT + NHID;   // [24]

    mega<<<GRID, 256>>>(inp, hidden, enc_outs, emb_W, attn_W, attn_b,
                        comb_W, comb_b, W_ih, W_hh, b_ih, b_hh,
                        out_W, out_b, logp, hout, attnw);
}

// round 12
// speedup vs baseline: 1.0166x; 1.0166x over previous
#include <cuda_runtime.h>
#include <math.h>

#define NHID 1024
#define NOUT 50257
#define MAXLEN 24
#define NTILE ((NOUT + 7) / 8)      // 6283
#define NFIN 64                     // finisher blocks
#define SLICE ((NOUT + NFIN - 1) / NFIN)   // 786

// -------- device scratch --------
__device__ float g_x[NHID];
__device__ float g_gh[3 * NHID];
__device__ float g_h[NHID];
__device__ float g_logits[NOUT];
__device__ float g_pm[NTILE];
__device__ float g_ps[NTILE];
__device__ unsigned g_ticket;       // epoch counter, never reset

__device__ __forceinline__ float wredsum(float v) {
    #pragma unroll
    for (int o = 16; o; o >>= 1) v += __shfl_xor_sync(0xffffffffu, v, o);
    return v;
}
__device__ __forceinline__ float wredmax(float v) {
    #pragma unroll
    for (int o = 16; o; o >>= 1) v = fmaxf(v, __shfl_xor_sync(0xffffffffu, v, o));
    return v;
}
__device__ __forceinline__ float sigm(float x) { return 1.f / (1.f + expf(-x)); }
__device__ __forceinline__ float dot4(float4 a, float4 b) {
    return a.x * b.x + a.y * b.y + a.z * b.z + a.w * b.w;
}

// ========== K1a: attention(redundant)+comb (blocks 0..127) | gh (blocks 128..511) ==========
__global__ void __launch_bounds__(256)
k1a(const int* __restrict__ inp,
    const float* __restrict__ hidden,
    const float* __restrict__ enc_outs,
    const float* __restrict__ emb_W,
    const float* __restrict__ attn_W,
    const float* __restrict__ attn_b,
    const float* __restrict__ comb_W,
    const float* __restrict__ comb_b,
    const float* __restrict__ W_hh,
    const float* __restrict__ b_hh,
    float* __restrict__ attnw_out) {
    __shared__ float sv[2 * NHID];
    __shared__ float sscore[32];
    __shared__ float sw[MAXLEN];
    const int t = threadIdx.x, b = blockIdx.x;
    const int warp = t >> 5, lane = t & 31;
    float4* sv4 = (float4*)sv;

    if (b >= 128) {
        // gh = W_hh @ h0 + b_hh : rows (b-128)*8+warp
        sv4[t] = ((const float4*)hidden)[t];
        __syncthreads();
        int r = (b - 128) * 8 + warp;
        const float4* w = (const float4*)(W_hh + (size_t)r * NHID);
        float acc = 0.f;
        #pragma unroll
        for (int q = 0; q < 8; q++) {
            int idx = lane + 32 * q;
            acc += dot4(__ldcs(w + idx), sv4[idx]);
        }
        acc = wredsum(acc);
        if (lane == 0) g_gh[r] = acc + b_hh[r];
        return;
    }

    // --- redundant local attention ---
    sv4[t] = ((const float4*)(emb_W + (size_t)inp[0] * NHID))[t];
    sv4[256 + t] = ((const float4*)hidden)[t];
    __syncthreads();

    for (int r = warp; r < MAXLEN; r += 8) {
        const float4* w = (const float4*)(attn_W + (size_t)r * (2 * NHID));
        float acc = 0.f;
        #pragma unroll
        for (int q = 0; q < 16; q++) {
            int idx = lane + 32 * q;
            acc += dot4(w[idx], sv4[idx]);
        }
        acc = wredsum(acc);
        if (lane == 0) sscore[r] = acc + attn_b[r];
    }
    __syncthreads();

    if (warp == 0) {
        float v = (lane < MAXLEN) ? sscore[lane] : -INFINITY;
        float m = wredmax(v);
        float p = (lane < MAXLEN) ? expf(v - m) : 0.f;
        float s = wredsum(p);
        float wv = p / s;
        if (lane < MAXLEN) {
            sw[lane] = wv;
            if (b == 0) attnw_out[lane] = wv;
        }
    }
    __syncthreads();

    // context -> sv upper half (sv = [embedded, context])
    {
        const float4* enc4 = (const float4*)enc_outs;
        float4 acc = make_float4(0.f, 0.f, 0.f, 0.f);
        #pragma unroll
        for (int m2 = 0; m2 < MAXLEN; m2++) {
            float wv = sw[m2];
            float4 v = enc4[m2 * 256 + t];
            acc.x += wv * v.x; acc.y += wv * v.y;
            acc.z += wv * v.z; acc.w += wv * v.w;
        }
        __syncthreads();
        sv4[256 + t] = acc;
    }
    __syncthreads();

    // --- comb GEMV + relu ---
    int row = b * 8 + warp;
    const float4* w4 = (const float4*)(comb_W + (size_t)row * (2 * NHID));
    float acc = 0.f;
    #pragma unroll
    for (int k = 0; k < 16; k++) {
        int idx = lane + 32 * k;
        acc += dot4(__ldcs(w4 + idx), sv4[idx]);
    }
    acc = wredsum(acc);
    if (lane == 0) g_x[row] = fmaxf(acc + comb_b[row], 0.f);
}

// ========== K1b: gi + GRU gates (grid 128, warp per hidden unit) ==========
__global__ void __launch_bounds__(256)
k1b(const float* __restrict__ W_ih,
    const float* __restrict__ b_ih,
    const float* __restrict__ hidden,
    float* __restrict__ hout) {
    __shared__ float4 sx[256];
    const int t = threadIdx.x, b = blockIdx.x;
    const int warp = t >> 5, lane = t & 31;

    sx[t] = ((const float4*)g_x)[t];
    __syncthreads();

    int k = b * 8 + warp;
    const float4* wir = (const float4*)(W_ih + (size_t)k * NHID);
    const float4* wiz = (const float4*)(W_ih + (size_t)(k + NHID) * NHID);
    const float4* win = (const float4*)(W_ih + (size_t)(k + 2 * NHID) * NHID);

    float air = 0.f, aiz = 0.f, ain = 0.f;
    #pragma unroll
    for (int q = 0; q < 8; q++) {
        int idx = lane + 32 * q;
        float4 x4 = sx[idx];
        air += dot4(__ldcs(wir + idx), x4);
        aiz += dot4(__ldcs(wiz + idx), x4);
        ain += dot4(__ldcs(win + idx), x4);
    }
    air = wredsum(air); aiz = wredsum(aiz); ain = wredsum(ain);

    if (lane == 0) {
        float r = sigm(air + b_ih[k] + g_gh[k]);
        float z = sigm(aiz + b_ih[NHID + k] + g_gh[NHID + k]);
        float n = tanhf(ain + b_ih[2 * NHID + k] + r * g_gh[2 * NHID + k]);
        float hnew = (1.f - z) * n + z * hidden[k];
        g_h[k] = hnew;
        hout[k] = hnew;
    }
}

// ========== K2: logits GEMV (grid 6283) + ticket epilogue (last 64 blocks) ==========
__global__ void __launch_bounds__(256)
k2(const float* __restrict__ out_W,
   const float* __restrict__ out_b,
   float* __restrict__ logp) {
    __shared__ float4 sh[256];
    __shared__ float slog[8];
    __shared__ float sred[512];
    __shared__ unsigned s_pos, s_end;
    const int t = threadIdx.x, b = blockIdx.x;
    const int warp = t >> 5, lane = t & 31;

    sh[t] = ((const float4*)g_h)[t];
    __syncthreads();

    int row = b * 8 + warp;
    float y = -INFINITY;
    if (row < NOUT) {
        const float4* w = (const float4*)(out_W + (size_t)row * NHID);
        float acc = 0.f;
        #pragma unroll
        for (int k = 0; k < 8; k++) {
            int idx = lane + 32 * k;
            acc += dot4(__ldcs(w + idx), sh[idx]);
        }
        acc = wredsum(acc);
        if (lane == 0) {
            y = acc + out_b[row];
            g_logits[row] = y;
        }
    }
    if (lane == 0) slog[warp] = y;
    __syncthreads();

    if (warp == 0) {
        float v = (lane < 8) ? slog[lane] : -INFINITY;
        float m = wredmax(v);
        float e = (lane < 8 && v > -INFINITY) ? __expf(v - m) : 0.f;
        e = wredsum(e);
        if (lane == 0) {
            g_pm[b] = m;
            g_ps[b] = e;
        }
    }
    __syncthreads();

    // ---- epoch ticket ----
    if (t == 0) {
        __threadfence();
        unsigned old = atomicAdd(&g_ticket, 1u);
        s_pos = old % NTILE;                       // position within this launch's epoch
        s_end = old - s_pos + NTILE;               // epoch end value
    }
    __syncthreads();
    unsigned pos = s_pos;
    if (pos < NTILE - NFIN) return;                // not a finisher

    // finisher: wait for all blocks of this epoch
    if (t == 0) {
        volatile unsigned* p = &g_ticket;
        while (*p < s_end) { __nanosleep(64); }
        __threadfence();
    }
    __syncthreads();

    // redundant reduce of 6283 partials
    float m = -INFINITY, s = 0.f;
    for (int i = t; i < NTILE; i += 256) {
        float mb = g_pm[i], sb = g_ps[i];
        if (mb > m) { s = s * __expf(m - mb) + sb; m = mb; }
        else        { s += sb * __expf(mb - m); }
    }
    sred[t] = m; sred[256 + t] = s;
    __syncthreads();
    for (int o = 128; o; o >>= 1) {
        if (t < o) {
            float m1 = sred[t], s1 = sred[256 + t];
            float m2 = sred[t + o], s2 = sred[256 + t + o];
            float M = fmaxf(m1, m2);
            float S = (s1 > 0.f ? s1 * __expf(m1 - M) : 0.f) +
                      (s2 > 0.f ? s2 * __expf(m2 - M) : 0.f);
            sred[t] = M; sred[256 + t] = S;
        }
        __syncthreads();
    }
    float C = sred[0] + logf(sred[256]);

    // write this finisher's logp slice
    int idx = (int)(pos - (NTILE - NFIN));         // 0..63
    int lo = idx * SLICE;
    int hi = min(lo + SLICE, NOUT);
    for (int i = lo + t; i < hi; i += 256)
        logp[i] = g_logits[i] - C;
}

extern "C" void kernel_launch(void* const* d_in, const int* in_sizes, int n_in,
                              void* d_out, int out_size) {
    const int*   inp      = (const int*)  d_in[0];
    const float* hidden   = (const float*)d_in[1];
    const float* enc_outs = (const float*)d_in[3];
    const float* emb_W    = (const float*)d_in[4];
    const float* attn_W   = (const float*)d_in[5];
    const float* attn_b   = (const float*)d_in[6];
    const float* comb_W   = (const float*)d_in[7];
    const float* comb_b   = (const float*)d_in[8];
    const float* W_ih     = (const float*)d_in[9];
    const float* W_hh     = (const float*)d_in[10];
    const float* b_ih     = (const float*)d_in[11];
    const float* b_hh     = (const float*)d_in[12];
    const float* out_W    = (const float*)d_in[13];
    const float* out_b    = (const float*)d_in[14];

    float* out   = (float*)d_out;
    float* logp  = out;                 // [50257]
    float* hout  = out + NOUT;          // [1024]
    float* attnw = out + NOUT + NHID;   // [24]

    k1a<<<512, 256>>>(inp, hidden, enc_outs, emb_W, attn_W, attn_b,
                      comb_W, comb_b, W_hh, b_hh, attnw);
    k1b<<<128, 256>>>(W_ih, b_ih, hidden, hout);
    k2<<<NTILE, 256>>>(out_W, out_b, logp);
}